// round 16
// baseline (speedup 1.0000x reference)
#include <cuda_runtime.h>
#include <cuda_bf16.h>

#define FULL_MASK 0xFFFFFFFFu

// R15 base (best: 106.5us wall / 102.3us ncu) with straggler rounds widened
// from 8 to 12 columns (3 concurrent gathers per lane, one __any_sync per
// round). Evidence: 4-col rounds (105.2) < 8-col rounds (102.3) — straggler
// speculative gathers are cheaper than serialized round trips, since they
// only occur on the ~20% straggler path while the E[max] decide tail gates
// every warp's 32 store instructions. Max rounds drops 8 -> 5.
// Decide: 4 lanes/row, 8 rows/warp, chunk 0 = cols 1..4 (col 0 = self,
// never gathered), strict '>' matches reference diff < 0. All-32-bit
// indexing; write phase = 4 dist bursts then 4 nidx bursts (512B/instr).
__global__ void __launch_bounds__(128, 16)
dgb_kernel(const float4* __restrict__ dist4,
           const int*    __restrict__ nidx,
           const float*  __restrict__ score,
           float4* __restrict__ dist_out4,
           float4* __restrict__ nidx_out4,
           int V)
{
    int warp_id = (int)(((unsigned)blockIdx.x * blockDim.x + threadIdx.x) >> 5);
    int lane = threadIdx.x & 31;
    int g = lane >> 2;                 // row group within warp: 0..7
    int l = lane & 3;                  // lane within group: 0..3
    unsigned grpmask = 0xFu << (g << 2);

    int row = warp_id * 8 + g;
    bool valid = row < V;
    int srow = valid ? row : 0;

    float sv = valid ? __ldg(score + row) : 3.0f;   // >1 => never beaten
    const int* nrow = nidx + (unsigned)srow * 64u;

    // ---- chunk 0: cols 1..4 ----
    bool cond;
    {
        int ni = __ldg(nrow + 1 + l);
        bool beat = (ni >= 0) && (__ldg(score + ni) > sv);   // strict
        cond = __any_sync(grpmask, beat);
    }

    // ---- straggler loop: 12 cols per round (3 gathers/lane, concurrent) ----
    if (!cond) {
        #pragma unroll 1
        for (int j = 0; j < 5; ++j) {
            int colA = 5 + j * 12 + l;          // round j covers cols 5+12j..16+12j
            int colB = colA + 4;
            int colC = colA + 8;
            int niA = (colA < 64) ? __ldg(nrow + colA) : -1;
            int niB = (colB < 64) ? __ldg(nrow + colB) : -1;
            int niC = (colC < 64) ? __ldg(nrow + colC) : -1;
            float vA = __ldg(score + max(niA, 0));
            float vB = __ldg(score + max(niB, 0));
            float vC = __ldg(score + max(niC, 0));
            bool beat = ((niA >= 0) & (vA > sv)) |
                        ((niB >= 0) & (vB > sv)) |
                        ((niC >= 0) & (vC > sv));
            if (__any_sync(grpmask, beat)) { cond = true; break; }
        }
    }

    // Publish cond bits for all 8 rows of this warp (bit at lane g*4).
    unsigned bal = __ballot_sync(FULL_MASK, cond);

    // ---- write phase: contiguous streaming over the warp's 8 rows ----
    int warp_row0 = warp_id * 8;
    unsigned gbase = (unsigned)warp_row0 * 16u;   // float4 idx (max 16M)
    const int4* nidx4 = (const int4*)nidx;

    // dist stores first: 4 x 512B contiguous bursts to one region
    #pragma unroll
    for (int t = 0; t < 4; ++t) {
        int vec = t * 32 + lane;       // 0..127 within warp region
        int row_local = vec >> 4;      // 0..7
        int rr = warp_row0 + row_local;
        if (rr >= V) continue;
        unsigned idx = gbase + (unsigned)vec;
        bool c = (bal >> (row_local << 2)) & 1u;
        float4 dv = c ? make_float4(0.f, 0.f, 0.f, 0.f)
                      : __ldcs(dist4 + idx);
        dist_out4[idx] = dv;
    }

    // then nidx stores: 4 x 512B contiguous bursts to the other region
    #pragma unroll
    for (int t = 0; t < 4; ++t) {
        int vec = t * 32 + lane;
        int row_local = vec >> 4;
        int within = vec & 15;
        int rr = warp_row0 + row_local;
        if (rr >= V) continue;
        unsigned idx = gbase + (unsigned)vec;
        bool c = (bal >> (row_local << 2)) & 1u;

        float4 nv;
        if (c) {
            nv = make_float4(-1.f, -1.f, -1.f, -1.f);
            if (within == 0) nv.x = (float)rr;
        } else {
            int4 niv = __ldcs(nidx4 + idx);
            nv = make_float4((float)niv.x, (float)niv.y,
                             (float)niv.z, (float)niv.w);
        }
        nidx_out4[idx] = nv;
    }
}

extern "C" void kernel_launch(void* const* d_in, const int* in_sizes, int n_in,
                              void* d_out, int out_size)
{
    const float* dist  = (const float*)d_in[0];   // [V, 64] f32
    const int*   nidx  = (const int*)d_in[1];     // [V, 64] i32
    const float* score = (const float*)d_in[2];   // [V, 1]  f32

    int V = in_sizes[2];                          // score element count == V

    float* out      = (float*)d_out;
    float* dist_out = out;                        // first V*64 floats
    float* nidx_out = out + (long long)V * 64;    // second V*64 (ints as f32)

    // 4 lanes per row -> V*4 threads
    long long total_threads = (long long)V * 4;
    int threads = 128;
    long long blocks = (total_threads + threads - 1) / threads;

    dgb_kernel<<<(unsigned int)blocks, threads>>>(
        (const float4*)dist, nidx, score,
        (float4*)dist_out, (float4*)nidx_out, V);
}

// round 17
// speedup vs baseline: 1.0222x; 1.0222x over previous
#include <cuda_runtime.h>
#include <cuda_bf16.h>

#define FULL_MASK 0xFFFFFFFFu

// R15 structure (best: 106.5us wall / 102.3us ncu) + __launch_bounds__(128,16)
// isolated from R16 (where occupancy rose 80.4->85.2% but was masked by the
// 12-col straggler regression). Straggler width curve measured: 4->105.2,
// 8->102.3 (optimum), 12->105.5 — this kernel keeps 8.
// Decide: 4 lanes/row, 8 rows/warp, chunk 0 = cols 1..4 (col 0 = self,
// never gathered), straggler rounds = two 4-col chunks per ballot, strict
// '>' matches reference diff < 0. All-32-bit indexing; write phase = 4 dist
// bursts then 4 nidx bursts (512B per store instruction, warp-coherent).
__global__ void __launch_bounds__(128, 16)
dgb_kernel(const float4* __restrict__ dist4,
           const int*    __restrict__ nidx,
           const float*  __restrict__ score,
           float4* __restrict__ dist_out4,
           float4* __restrict__ nidx_out4,
           int V)
{
    int warp_id = (int)(((unsigned)blockIdx.x * blockDim.x + threadIdx.x) >> 5);
    int lane = threadIdx.x & 31;
    int g = lane >> 2;                 // row group within warp: 0..7
    int l = lane & 3;                  // lane within group: 0..3
    unsigned grpmask = 0xFu << (g << 2);

    int row = warp_id * 8 + g;
    bool valid = row < V;
    int srow = valid ? row : 0;

    float sv = valid ? __ldg(score + row) : 3.0f;   // >1 => never beaten
    const int* nrow = nidx + (unsigned)srow * 64u;

    // ---- chunk 0: cols 1..4 ----
    bool cond;
    {
        int ni = __ldg(nrow + 1 + l);
        bool beat = (ni >= 0) && (__ldg(score + ni) > sv);   // strict
        cond = __any_sync(grpmask, beat);
    }

    // ---- straggler loop: two 4-col chunks per ballot (8 cols/round) ----
    if (!cond) {
        #pragma unroll 1
        for (int j = 1; j < 16; j += 2) {
            int colA = (j << 2) + 1 + l;        // 5..64  (64 guarded)
            int colB = colA + 4;
            int niA = (colA < 64) ? __ldg(nrow + colA) : -1;
            int niB = (colB < 64) ? __ldg(nrow + colB) : -1;
            float vA = __ldg(score + max(niA, 0));
            float vB = __ldg(score + max(niB, 0));
            bool beat = ((niA >= 0) & (vA > sv)) |
                        ((niB >= 0) & (vB > sv));
            if (__any_sync(grpmask, beat)) { cond = true; break; }
        }
    }

    // Publish cond bits for all 8 rows of this warp (bit at lane g*4).
    unsigned bal = __ballot_sync(FULL_MASK, cond);

    // ---- write phase: contiguous streaming over the warp's 8 rows ----
    int warp_row0 = warp_id * 8;
    unsigned gbase = (unsigned)warp_row0 * 16u;   // float4 idx (max 16M)
    const int4* nidx4 = (const int4*)nidx;

    // dist stores first: 4 x 512B contiguous bursts to one region
    #pragma unroll
    for (int t = 0; t < 4; ++t) {
        int vec = t * 32 + lane;       // 0..127 within warp region
        int row_local = vec >> 4;      // 0..7
        int rr = warp_row0 + row_local;
        if (rr >= V) continue;
        unsigned idx = gbase + (unsigned)vec;
        bool c = (bal >> (row_local << 2)) & 1u;
        float4 dv = c ? make_float4(0.f, 0.f, 0.f, 0.f)
                      : __ldcs(dist4 + idx);
        dist_out4[idx] = dv;
    }

    // then nidx stores: 4 x 512B contiguous bursts to the other region
    #pragma unroll
    for (int t = 0; t < 4; ++t) {
        int vec = t * 32 + lane;
        int row_local = vec >> 4;
        int within = vec & 15;
        int rr = warp_row0 + row_local;
        if (rr >= V) continue;
        unsigned idx = gbase + (unsigned)vec;
        bool c = (bal >> (row_local << 2)) & 1u;

        float4 nv;
        if (c) {
            nv = make_float4(-1.f, -1.f, -1.f, -1.f);
            if (within == 0) nv.x = (float)rr;
        } else {
            int4 niv = __ldcs(nidx4 + idx);
            nv = make_float4((float)niv.x, (float)niv.y,
                             (float)niv.z, (float)niv.w);
        }
        nidx_out4[idx] = nv;
    }
}

extern "C" void kernel_launch(void* const* d_in, const int* in_sizes, int n_in,
                              void* d_out, int out_size)
{
    const float* dist  = (const float*)d_in[0];   // [V, 64] f32
    const int*   nidx  = (const int*)d_in[1];     // [V, 64] i32
    const float* score = (const float*)d_in[2];   // [V, 1]  f32

    int V = in_sizes[2];                          // score element count == V

    float* out      = (float*)d_out;
    float* dist_out = out;                        // first V*64 floats
    float* nidx_out = out + (long long)V * 64;    // second V*64 (ints as f32)

    // 4 lanes per row -> V*4 threads
    long long total_threads = (long long)V * 4;
    int threads = 128;
    long long blocks = (total_threads + threads - 1) / threads;

    dgb_kernel<<<(unsigned int)blocks, threads>>>(
        (const float4*)dist, nidx, score,
        (float4*)dist_out, (float4*)nidx_out, V);
}